// round 15
// baseline (speedup 1.0000x reference)
#include <cuda_runtime.h>
#include <cuda_bf16.h>
#include <stdint.h>

#define Tt 512
#define Bt 128
#define KK 32
#define NEGV (-10000.0f)

// ---------------- scratch (static device globals; no runtime alloc) ----------------
__device__ uint4          g_wp2[2 * 16 * 512];                  // packed bf16x8 Whh [dir][q4][g]
__device__ unsigned       g_wihb[2 * 512 * 32];                 // bf16 Wih [dir][g][64] as u32 pairs
__device__ __nv_bfloat16  g_zx[2ll * 65536 * 512];              // x-projection [dir][m][g]  128 MB
__device__ __nv_bfloat16  g_h[2ll * Tt * Bt * 128];             // [dir][t][b][j]  32 MB
__device__ float          g_feats[(size_t)Bt * Tt * KK];        // [b][t][k]  8 MB
__device__ float          g_logZ[Bt];
__device__ float          g_gold[Bt];

// ---------------- helpers ----------------
__device__ __forceinline__ __nv_bfloat162 u2b(unsigned u) {
    __nv_bfloat162 r; *reinterpret_cast<unsigned*>(&r) = u; return r;
}
__device__ __forceinline__ unsigned b2u(__nv_bfloat162 b) {
    return *reinterpret_cast<unsigned*>(&b);
}
__device__ __forceinline__ float tanh_f(float x) {
    float y; asm("tanh.approx.f32 %0, %1;" : "=f"(y) : "f"(x)); return y;
}
__device__ __forceinline__ float sig_f(float x) { return 0.5f * tanh_f(0.5f * x) + 0.5f; }
__device__ __forceinline__ float rcp_f(float x) {
    float y; asm("rcp.approx.f32 %0, %1;" : "=f"(y) : "f"(x)); return y;
}
__device__ __forceinline__ void mma16816(float& c0, float& c1, float& c2, float& c3,
                                         unsigned a0, unsigned a1, unsigned a2, unsigned a3,
                                         unsigned b0, unsigned b1) {
    asm volatile("mma.sync.aligned.m16n8k16.row.col.f32.bf16.bf16.f32 "
                 "{%0,%1,%2,%3}, {%4,%5,%6,%7}, {%8,%9}, {%0,%1,%2,%3};"
                 : "+f"(c0), "+f"(c1), "+f"(c2), "+f"(c3)
                 : "r"(a0), "r"(a1), "r"(a2), "r"(a3), "r"(b0), "r"(b1));
}

// ---------------- phase 0: pack Whh (bf16x8 per thread-gate) + Wih (bf16 rows) ------------
__global__ void prep_w_kernel(const float* __restrict__ Wih_f, const float* __restrict__ Whh_f,
                              const float* __restrict__ Wih_b, const float* __restrict__ Whh_b) {
    int idx = blockIdx.x * blockDim.x + threadIdx.x;   // 16384 + 32768 = 49152
    if (idx < 16384) {
        int dir = idx >> 13;
        int rem = idx & 8191;
        int q4 = rem >> 9, g = rem & 511;
        const float* Whh = dir ? Whh_b : Whh_f;
        unsigned p[4];
#pragma unroll
        for (int c = 0; c < 4; c++) {
            int d0 = q4 * 8 + 2 * c;
            p[c] = b2u(__floats2bfloat162_rn(Whh[g * 128 + d0], Whh[g * 128 + d0 + 1]));
        }
        g_wp2[idx] = make_uint4(p[0], p[1], p[2], p[3]);
    } else if (idx < 49152) {
        int i2 = idx - 16384;               // 0..32767
        int dir = i2 >> 14;
        int rem = i2 & 16383;
        int g = rem >> 5, p = rem & 31;
        const float* Wih = dir ? Wih_b : Wih_f;
        g_wihb[i2] = b2u(__floats2bfloat162_rn(Wih[g * 64 + 2 * p], Wih[g * 64 + 2 * p + 1]));
    }
}

// ---------------- phase 1: zx = x @ Wih^T — B register-resident, A double-buffered --------
// grid (64, 4, 2): CTA = (8-timestep group, n-quarter of 128 gates, dir).
// Each warp owns a fixed 32-gate strip: its 32 B-fragment u32 live in registers for all
// 8 timesteps. A (128 rows x 64 dims bf16) staged per timestep in fragment order
// [k0][row][9] (stride-9, conflict-free), double-buffered; one barrier per timestep.
#define ZXA 4608                       // u32 per A buffer (4*128*9)
#define ZX_SMEM (2 * ZXA * 4)          // 36864 bytes
__global__ void __launch_bounds__(256) zx_kernel(const int* __restrict__ sentences,
                                                 const float* __restrict__ emb) {
    extern __shared__ __align__(16) unsigned sm_u[];

    const int tid  = threadIdx.x;
    const int tgrp = blockIdx.x;          // timesteps tgrp*8 .. tgrp*8+7
    const int nq   = blockIdx.y;          // gate quarter (128 gates)
    const int dir  = blockIdx.z;

    const int w = tid >> 5, lane = tid & 31;
    const int g = lane >> 2, t = lane & 3;
    const int mwarp = w >> 2, nwarp = w & 3;      // 2 (m) x 4 (n)
    const int nbase = nq * 128 + nwarp * 32;

    // --- B fragments: 32 u32 in registers, loaded once from global (L2-resident) ---
    const unsigned* wu = g_wihb + dir * 16384;    // [512][32]
    unsigned breg[4][4][2];
#pragma unroll
    for (int k0 = 0; k0 < 4; k0++)
#pragma unroll
        for (int nt = 0; nt < 4; nt++) {
            int n = nbase + nt * 8 + g;
            breg[k0][nt][0] = wu[n * 32 + k0 * 8 + t];
            breg[k0][nt][1] = wu[n * 32 + k0 * 8 + 4 + t];
        }

    // --- A stage helper (inline twice): rows of emb -> bf16 pairs, fragment order ---
    const int srow = tid >> 1, shf = tid & 1;     // 2 threads per row
#define STAGE_A(buf, mt_)  do {                                                     \
        int tok = sentences[srow * Tt + (mt_)];                                     \
        const float4* e4 = (const float4*)(emb + (size_t)tok * 64 + shf * 32);      \
        _Pragma("unroll")                                                           \
        for (int q = 0; q < 8; q++) {                                               \
            float4 v = e4[q];                                                       \
            int pp0 = shf * 16 + 2 * q;                                             \
            int pp1 = pp0 + 1;                                                      \
            (buf)[(pp0 >> 3) * 1152 + srow * 9 + (pp0 & 7)] =                       \
                b2u(__floats2bfloat162_rn(v.x, v.y));                               \
            (buf)[(pp1 >> 3) * 1152 + srow * 9 + (pp1 & 7)] =                       \
                b2u(__floats2bfloat162_rn(v.z, v.w));                               \
        }                                                                           \
    } while (0)

    STAGE_A(sm_u, tgrp * 8);
    __syncthreads();

    unsigned* zxu = (unsigned*)g_zx + (size_t)dir * 65536 * 256;

#pragma unroll 1
    for (int i = 0; i < 8; i++) {
        const int mtile = tgrp * 8 + i;
        unsigned* cur = sm_u + (i & 1) * ZXA;
        unsigned* nxt = sm_u + ((i + 1) & 1) * ZXA;
        if (i + 1 < 8) STAGE_A(nxt, mtile + 1);

#pragma unroll
        for (int miter = 0; miter < 2; miter++) {
            const int rbase = miter * 64 + mwarp * 32;

            unsigned a[4][2][4];
#pragma unroll
            for (int k0 = 0; k0 < 4; k0++)
#pragma unroll
                for (int mt = 0; mt < 2; mt++) {
                    int r0 = rbase + mt * 16;
                    a[k0][mt][0] = cur[k0 * 1152 + (r0 + g) * 9 + t];
                    a[k0][mt][1] = cur[k0 * 1152 + (r0 + 8 + g) * 9 + t];
                    a[k0][mt][2] = cur[k0 * 1152 + (r0 + g) * 9 + 4 + t];
                    a[k0][mt][3] = cur[k0 * 1152 + (r0 + 8 + g) * 9 + 4 + t];
                }

            float c[2][4][4];
#pragma unroll
            for (int mt = 0; mt < 2; mt++)
#pragma unroll
                for (int nt = 0; nt < 4; nt++)
#pragma unroll
                    for (int q = 0; q < 4; q++) c[mt][nt][q] = 0.0f;

#pragma unroll
            for (int k0 = 0; k0 < 4; k0++)
#pragma unroll
                for (int mt = 0; mt < 2; mt++)
#pragma unroll
                    for (int nt = 0; nt < 4; nt++)
                        mma16816(c[mt][nt][0], c[mt][nt][1], c[mt][nt][2], c[mt][nt][3],
                                 a[k0][mt][0], a[k0][mt][1], a[k0][mt][2], a[k0][mt][3],
                                 breg[k0][nt][0], breg[k0][nt][1]);

            // epilogue: c0,c1 -> row g col 2t,2t+1 ; c2,c3 -> row g+8
#pragma unroll
            for (int mt = 0; mt < 2; mt++) {
                int r0 = mtile * 128 + rbase + mt * 16 + g;
#pragma unroll
                for (int nt = 0; nt < 4; nt++) {
                    int np = (nbase + nt * 8) / 2 + t;
                    zxu[(size_t)r0 * 256 + np]       = b2u(__floats2bfloat162_rn(c[mt][nt][0], c[mt][nt][1]));
                    zxu[(size_t)(r0 + 8) * 256 + np] = b2u(__floats2bfloat162_rn(c[mt][nt][2], c[mt][nt][3]));
                }
            }
        }
        __syncthreads();
    }
#undef STAGE_A
}

// ---------------- phase 2: BiLSTM recurrence, h-part only (R13 version, known-good) -------
// grid = 128: dir = blk>>6, group = blk&63 -> batch rows {2g, 2g+1}
__global__ void __launch_bounds__(512, 1)
lstm_kernel(const float* __restrict__ bias_f, const float* __restrict__ bias_b) {
    __shared__ unsigned inb[2 * 64];      // h bf16 pairs, [chain][64]
    __shared__ float zb[2 * 512];

    const int dir = blockIdx.x >> 6;
    const int b0  = (blockIdx.x & 63) * 2;
    const int g   = threadIdx.x;

    const uint4* wp = g_wp2 + dir * (16 * 512);
    __nv_bfloat162 w2[64];
#pragma unroll
    for (int q4 = 0; q4 < 16; q4++) {
        uint4 t = wp[q4 * 512 + g];
        w2[4 * q4 + 0] = u2b(t.x);
        w2[4 * q4 + 1] = u2b(t.y);
        w2[4 * q4 + 2] = u2b(t.z);
        w2[4 * q4 + 3] = u2b(t.w);
    }
    const float bz = (dir ? bias_b : bias_f)[g];
    if (g < 128) inb[g] = 0u;

    const __nv_bfloat16* zxb = g_zx + (size_t)dir * 65536 * 512;
    __nv_bfloat16 zx0c, zx1c, zx0n, zx1n;
    {
        int u0 = dir ? 511 : 0, u1 = dir ? 510 : 1;
        zx0c = zxb[((size_t)(u0 * 128 + b0)) * 512 + g];
        zx1c = zxb[((size_t)(u0 * 128 + b0 + 1)) * 512 + g];
        zx0n = zxb[((size_t)(u1 * 128 + b0)) * 512 + g];
        zx1n = zxb[((size_t)(u1 * 128 + b0 + 1)) * 512 + g];
    }
    float c = 0.0f;
    __syncthreads();

    for (int s = 0; s < Tt; s++) {
        // prefetch zx(s+2); raw bf16 regs, consumed 2 steps later
        __nv_bfloat16 p0 = __float2bfloat16(0.f), p1 = p0;
        if (s + 2 < Tt) {
            int u2 = dir ? (509 - s) : (s + 2);
            p0 = zxb[((size_t)(u2 * 128 + b0)) * 512 + g];
            p1 = zxb[((size_t)(u2 * 128 + b0 + 1)) * 512 + g];
        }

        // h-part GEMM: thread g -> z[r][g], 128 dims, bf16 HFMA2
        __nv_bfloat162 a00 = u2b(0u), a01 = u2b(0u), a10 = u2b(0u), a11 = u2b(0u);
        const uint4* h0 = (const uint4*)inb;
        const uint4* h1 = (const uint4*)(inb + 64);
#pragma unroll
        for (int k = 0; k < 16; k++) {
            uint4 av = h0[k], bv = h1[k];
            a00 = __hfma2(w2[4 * k + 0], u2b(av.x), a00);
            a01 = __hfma2(w2[4 * k + 1], u2b(av.y), a01);
            a00 = __hfma2(w2[4 * k + 2], u2b(av.z), a00);
            a01 = __hfma2(w2[4 * k + 3], u2b(av.w), a01);
            a10 = __hfma2(w2[4 * k + 0], u2b(bv.x), a10);
            a11 = __hfma2(w2[4 * k + 1], u2b(bv.y), a11);
            a10 = __hfma2(w2[4 * k + 2], u2b(bv.z), a10);
            a11 = __hfma2(w2[4 * k + 3], u2b(bv.w), a11);
        }
        {
            float2 f0 = __bfloat1622float2(a00), f1 = __bfloat1622float2(a01);
            zb[g] = (f0.x + f0.y) + (f1.x + f1.y) + bz + __bfloat162float(zx0c);
            f0 = __bfloat1622float2(a10); f1 = __bfloat1622float2(a11);
            zb[512 + g] = (f0.x + f0.y) + (f1.x + f1.y) + bz + __bfloat162float(zx1c);
        }
        __syncthreads();

        if (g < 256) {
            int r = g >> 7, j = g & 127;
            const float* zr = zb + r * 512;
            float zi = zr[j], zf = zr[128 + j], zg_ = zr[256 + j], zo = zr[384 + j];
            c = sig_f(zf) * c + sig_f(zi) * tanh_f(zg_);
            float h = sig_f(zo) * tanh_f(c);
            __nv_bfloat16 hb = __float2bfloat16(h);
            ((__nv_bfloat16*)(inb + r * 64))[j] = hb;
            int u = dir ? (Tt - 1 - s) : s;
            g_h[((size_t)dir * Tt + u) * (Bt * 128) + (b0 + r) * 128 + j] = hb;
        }
        zx0c = zx0n; zx1c = zx1n; zx0n = p0; zx1n = p1;
        __syncthreads();
    }
}

// ---------------- phase 3: feats[b][t][k] = [h_f|h_b] . W_out[k] + b_out[k] ----------------
#define FEATS_SMEM (32 * 132 * 4 + 64 * 128 * 4)   // 49664
__global__ void __launch_bounds__(256)
feats_kernel(const float* __restrict__ W_out, const float* __restrict__ b_out) {
    extern __shared__ __align__(16) char sm[];
    unsigned* Ws = (unsigned*)sm;                  // [32][132] bf16 pairs (padded)
    unsigned* Hs = (unsigned*)(sm + 32 * 132 * 4); // [64][128] bf16 pairs
    int b  = blockIdx.x >> 3;
    int t0 = (blockIdx.x & 7) * 64;
    int tid = threadIdx.x;

    for (int i = tid; i < 32 * 128; i += 256) {
        int k = i >> 7, d2 = i & 127;
        Ws[k * 132 + d2] = b2u(__floats2bfloat162_rn(W_out[k * 256 + 2 * d2],
                                                     W_out[k * 256 + 2 * d2 + 1]));
    }
    const unsigned* ghu = (const unsigned*)g_h;
    for (int i = tid; i < 64 * 128; i += 256) {
        int t = i >> 7, d2 = i & 127;
        int dirb = d2 >> 6, j2 = d2 & 63;
        Hs[t * 128 + d2] = ghu[(((size_t)dirb * Tt + (t0 + t)) * Bt + b) * 64 + j2];
    }
    __syncthreads();

    int k = tid & 31, tg = tid >> 5;
    const uint4* wk = (const uint4*)(Ws + k * 132);
    __nv_bfloat162 acc[8];
#pragma unroll
    for (int tt = 0; tt < 8; tt++) acc[tt] = u2b(0u);
#pragma unroll 4
    for (int q4 = 0; q4 < 32; q4++) {
        uint4 wv = wk[q4];
#pragma unroll
        for (int tt = 0; tt < 8; tt++) {
            uint4 hv = ((const uint4*)(Hs + (tg * 8 + tt) * 128))[q4];
            acc[tt] = __hfma2(u2b(wv.x), u2b(hv.x), acc[tt]);
            acc[tt] = __hfma2(u2b(wv.y), u2b(hv.y), acc[tt]);
            acc[tt] = __hfma2(u2b(wv.z), u2b(hv.z), acc[tt]);
            acc[tt] = __hfma2(u2b(wv.w), u2b(hv.w), acc[tt]);
        }
    }
    float bo = b_out[k];
#pragma unroll
    for (int tt = 0; tt < 8; tt++) {
        float2 f = __bfloat1622float2(acc[tt]);
        g_feats[((size_t)b * Tt + (t0 + tg * 8 + tt)) * KK + k] = f.x + f.y + bo;
    }
}

// ---------------- phase 4: CRF forward logZ (linear ratio-space) + gold score fused -------
__global__ void __launch_bounds__(32)
crf_kernel(const float* __restrict__ trans, const int* __restrict__ tags) {
    const unsigned full = 0xffffffffu;
    __shared__ float qs[2][32];
    int b = blockIdx.x;
    int j = threadIdx.x;
    float et[32];
#pragma unroll
    for (int i = 0; i < 32; i++) et[i] = __expf(trans[j * 32 + i]);   // et[*][0] == 0
    float sumEt = 0.0f;
#pragma unroll
    for (int i = 1; i < 32; i++) sumEt += et[i];
    const float* fbase = g_feats + (size_t)b * Tt * KK;

    float fv0 = fbase[j] + NEGV + __logf(1.0f + sumEt);
    float A = __shfl_sync(full, fv0, 1);
    float qn = __expf(fv0 - A);
    qs[0][j] = qn;
    int buf = 0;
    float rb[4];
#pragma unroll
    for (int d = 0; d < 4; d++) rb[d] = fbase[(1 + d) * KK + j];
    __syncwarp();

    for (int t = 1; t < Tt; t += 4) {
        float ees[4];
#pragma unroll
        for (int d = 0; d < 4; d++) ees[d] = __expf(rb[d]);
#pragma unroll
        for (int d = 0; d < 4; d++) {
            int tn = t + 4 + d; tn = (tn < Tt) ? tn : (Tt - 1);
            rb[d] = fbase[tn * KK + j];
        }
#pragma unroll
        for (int d = 0; d < 4; d++) {
            if (t + d >= Tt) break;
            const float4* qv = (const float4*)qs[buf];
            float s0 = 0.f, s1 = 0.f, s2 = 0.f, s3 = 0.f;
#pragma unroll
            for (int i8 = 0; i8 < 8; i8++) {
                float4 v = qv[i8];
                s0 += et[4 * i8 + 0] * v.x;
                s1 += et[4 * i8 + 1] * v.y;
                s2 += et[4 * i8 + 2] * v.z;
                s3 += et[4 * i8 + 3] * v.w;
            }
            qn = ees[d] * ((s0 + s1) + (s2 + s3));
            if (d & 1) {
                float z = __shfl_sync(full, qn, 1);
                A += __logf(z);
                qn *= rcp_f(z);
            }
            buf ^= 1;
            qs[buf][j] = qn;
            __syncwarp();
        }
    }
    float ss = qn;
#pragma unroll
    for (int o = 16; o; o >>= 1) ss += __shfl_xor_sync(full, ss, o);
    if (j == 0) g_logZ[b] = A + __logf(ss) + NEGV;

    // ---- fused gold path score ----
    const int* tg = tags + b * Tt;
    float acc = 0.0f;
    for (int t = j; t < Tt; t += 32) {
        int cur = tg[t];
        int pv = t ? tg[t - 1] : 0;
        acc += trans[cur * 32 + pv] + fbase[t * KK + cur];
    }
#pragma unroll
    for (int o = 16; o; o >>= 1) acc += __shfl_xor_sync(full, acc, o);
    if (j == 0) g_gold[b] = acc + trans[tg[Tt - 1]];
}

// ---------------- phase 5: deterministic final reduce ----------------
__global__ void final_kernel(float* out) {
    __shared__ float sbuf[128];
    int tid = threadIdx.x;
    sbuf[tid] = g_logZ[tid] - g_gold[tid];
    __syncthreads();
    for (int s2 = 64; s2; s2 >>= 1) {
        if (tid < s2) sbuf[tid] += sbuf[tid + s2];
        __syncthreads();
    }
    if (tid == 0) out[0] = sbuf[0];
}

// ---------------- launch ----------------
extern "C" void kernel_launch(void* const* d_in, const int* in_sizes, int n_in,
                              void* d_out, int out_size) {
    const int*   sentences = (const int*)d_in[0];
    const int*   tags      = (const int*)d_in[1];
    const float* emb       = (const float*)d_in[2];
    const float* Wih_f     = (const float*)d_in[3];
    const float* Whh_f     = (const float*)d_in[4];
    const float* b_f       = (const float*)d_in[5];
    const float* Wih_b     = (const float*)d_in[6];
    const float* Whh_b     = (const float*)d_in[7];
    const float* b_b       = (const float*)d_in[8];
    const float* W_out     = (const float*)d_in[9];
    const float* b_out     = (const float*)d_in[10];
    const float* trans     = (const float*)d_in[11];

    cudaFuncSetAttribute(zx_kernel,    cudaFuncAttributeMaxDynamicSharedMemorySize, ZX_SMEM);
    cudaFuncSetAttribute(feats_kernel, cudaFuncAttributeMaxDynamicSharedMemorySize, FEATS_SMEM);

    prep_w_kernel<<<96, 512>>>(Wih_f, Whh_f, Wih_b, Whh_b);
    zx_kernel<<<dim3(64, 4, 2), 256, ZX_SMEM>>>(sentences, emb);
    lstm_kernel<<<128, 512>>>(b_f, b_b);
    feats_kernel<<<1024, 256, FEATS_SMEM>>>(W_out, b_out);
    crf_kernel<<<128, 32>>>(trans, tags);
    final_kernel<<<1, 128>>>((float*)d_out);
}

// round 16
// speedup vs baseline: 1.0500x; 1.0500x over previous
#include <cuda_runtime.h>
#include <cuda_bf16.h>
#include <stdint.h>

#define Tt 512
#define Bt 128
#define KK 32
#define NEGV (-10000.0f)

// ---------------- scratch (static device globals; no runtime alloc) ----------------
__device__ uint4          g_wp2[2 * 16 * 512];                  // packed bf16x8 Whh [dir][q4][g]
__device__ unsigned       g_wihb[2 * 512 * 32];                 // bf16 Wih [dir][g][64] as u32 pairs
__device__ __nv_bfloat16  g_zx[2ll * 65536 * 512];              // x-projection [dir][m][g]  128 MB
__device__ __nv_bfloat16  g_h[2ll * Tt * Bt * 128];             // [dir][t][b][j]  32 MB
__device__ float          g_feats[(size_t)Bt * Tt * KK];        // [b][t][k]  8 MB
__device__ float          g_logZ[Bt];
__device__ float          g_gold[Bt];

// ---------------- helpers ----------------
__device__ __forceinline__ __nv_bfloat162 u2b(unsigned u) {
    __nv_bfloat162 r; *reinterpret_cast<unsigned*>(&r) = u; return r;
}
__device__ __forceinline__ unsigned b2u(__nv_bfloat162 b) {
    return *reinterpret_cast<unsigned*>(&b);
}
__device__ __forceinline__ float tanh_f(float x) {
    float y; asm("tanh.approx.f32 %0, %1;" : "=f"(y) : "f"(x)); return y;
}
__device__ __forceinline__ float sig_f(float x) { return 0.5f * tanh_f(0.5f * x) + 0.5f; }
__device__ __forceinline__ float rcp_f(float x) {
    float y; asm("rcp.approx.f32 %0, %1;" : "=f"(y) : "f"(x)); return y;
}
__device__ __forceinline__ void mma16816(float& c0, float& c1, float& c2, float& c3,
                                         unsigned a0, unsigned a1, unsigned a2, unsigned a3,
                                         unsigned b0, unsigned b1) {
    asm volatile("mma.sync.aligned.m16n8k16.row.col.f32.bf16.bf16.f32 "
                 "{%0,%1,%2,%3}, {%4,%5,%6,%7}, {%8,%9}, {%0,%1,%2,%3};"
                 : "+f"(c0), "+f"(c1), "+f"(c2), "+f"(c3)
                 : "r"(a0), "r"(a1), "r"(a2), "r"(a3), "r"(b0), "r"(b1));
}

// ---------------- phase 0: pack Whh (bf16x8 per thread-gate) + Wih (bf16 rows) ------------
__global__ void prep_w_kernel(const float* __restrict__ Wih_f, const float* __restrict__ Whh_f,
                              const float* __restrict__ Wih_b, const float* __restrict__ Whh_b) {
    int idx = blockIdx.x * blockDim.x + threadIdx.x;   // 16384 + 32768 = 49152
    if (idx < 16384) {
        int dir = idx >> 13;
        int rem = idx & 8191;
        int q4 = rem >> 9, g = rem & 511;
        const float* Whh = dir ? Whh_b : Whh_f;
        unsigned p[4];
#pragma unroll
        for (int c = 0; c < 4; c++) {
            int d0 = q4 * 8 + 2 * c;
            p[c] = b2u(__floats2bfloat162_rn(Whh[g * 128 + d0], Whh[g * 128 + d0 + 1]));
        }
        g_wp2[idx] = make_uint4(p[0], p[1], p[2], p[3]);
    } else if (idx < 49152) {
        int i2 = idx - 16384;               // 0..32767
        int dir = i2 >> 14;
        int rem = i2 & 16383;
        int g = rem >> 5, p = rem & 31;
        const float* Wih = dir ? Wih_b : Wih_f;
        g_wihb[i2] = b2u(__floats2bfloat162_rn(Wih[g * 64 + 2 * p], Wih[g * 64 + 2 * p + 1]));
    }
}

// ---------------- phase 1: zx = x @ Wih^T — smem-staged mma.sync, 64-bit fragment loads ---
// grid (512, 2): CTA = (timestep, dir), 128 batch rows x 512 gates, K=64.  (R13 structure)
// Tiles staged as uint2[k0][row][t] where uint2 = (frag pair p=k0*8+t, pair p=k0*8+4+t):
// fragment fetch = ONE LDS.64 for (a0,a2)/(a1,a3)/(bf0,bf1).  Dense stride-4 layout is
// bank-pair-conflict-free (addr mod 16 = 4g+t, all distinct per half-warp).
#define ZX_SMEM (4 * 128 * 4 * 8 + 4 * 512 * 4 * 8)   // 16384 + 65536 = 81920
__global__ void __launch_bounds__(256, 2) zx_kernel(const int* __restrict__ sentences,
                                                    const float* __restrict__ emb) {
    extern __shared__ __align__(16) unsigned sm_u[];
    unsigned* As = sm_u;                    // uint2[4][128][4] viewed as u32
    unsigned* Bs = sm_u + 4 * 128 * 4 * 2;  // uint2[4][512][4] viewed as u32

    const int tid   = threadIdx.x;
    const int mtile = blockIdx.x;           // timestep t
    const int dir   = blockIdx.y;

    // --- stage A: 128 rows of emb (fp32) -> bf16 pairs, uint2-paired fragment order ---
    {
        int row = tid >> 1, hf = tid & 1;   // 2 threads per row
        int tok = sentences[row * Tt + mtile];
        const float4* e4 = (const float4*)(emb + (size_t)tok * 64 + hf * 32);
#pragma unroll
        for (int q = 0; q < 8; q++) {
            float4 v = e4[q];
            int pp0 = hf * 16 + 2 * q;      // global bf16-pair index
            int pp1 = pp0 + 1;
            int s0 = pp0 & 7, s1 = pp1 & 7;
            As[(((pp0 >> 3) * 128 + row) * 4 + (s0 & 3)) * 2 + (s0 >> 2)] =
                b2u(__floats2bfloat162_rn(v.x, v.y));
            As[(((pp1 >> 3) * 128 + row) * 4 + (s1 & 3)) * 2 + (s1 >> 2)] =
                b2u(__floats2bfloat162_rn(v.z, v.w));
        }
    }
    // --- stage B: 512 gate rows of Wih (bf16 pairs), uint2-paired fragment order ---
    {
        const uint4* wu4 = (const uint4*)(g_wihb + dir * 16384);
        for (int i = tid; i < 512 * 8; i += 256) {
            int n = i >> 3, ch = i & 7;
            uint4 v = wu4[n * 8 + ch];
            unsigned vv[4] = {v.x, v.y, v.z, v.w};
#pragma unroll
            for (int c = 0; c < 4; c++) {
                int p = ch * 4 + c;
                int s = p & 7;
                Bs[(((p >> 3) * 512 + n) * 4 + (s & 3)) * 2 + (s >> 2)] = vv[c];
            }
        }
    }
    __syncthreads();

    const int w = tid >> 5, lane = tid & 31;
    const int g = lane >> 2, t = lane & 3;
    const int mwarp = w >> 2, nwarp = w & 3;
    unsigned* zxu = (unsigned*)g_zx + (size_t)dir * 65536 * 256;
    const uint2* As2 = (const uint2*)As;
    const uint2* Bs2 = (const uint2*)Bs;

#pragma unroll 1
    for (int miter = 0; miter < 2; miter++) {
        const int rbase = miter * 64 + mwarp * 32;

        // A fragments: one LDS.64 yields (a0,a2) / (a1,a3)
        unsigned a[4][2][4];
#pragma unroll
        for (int k0 = 0; k0 < 4; k0++)
#pragma unroll
            for (int mt = 0; mt < 2; mt++) {
                int r0 = rbase + mt * 16;
                uint2 lo = As2[(k0 * 128 + r0 + g) * 4 + t];
                uint2 hi = As2[(k0 * 128 + r0 + 8 + g) * 4 + t];
                a[k0][mt][0] = lo.x;
                a[k0][mt][1] = hi.x;
                a[k0][mt][2] = lo.y;
                a[k0][mt][3] = hi.y;
            }

#pragma unroll 1
        for (int niter = 0; niter < 4; niter++) {
            const int n0 = niter * 128 + nwarp * 32;
            float c[2][4][4];
#pragma unroll
            for (int mt = 0; mt < 2; mt++)
#pragma unroll
                for (int nt = 0; nt < 4; nt++)
#pragma unroll
                    for (int i = 0; i < 4; i++) c[mt][nt][i] = 0.0f;

#pragma unroll
            for (int k0 = 0; k0 < 4; k0++) {
                unsigned bf[4][2];
#pragma unroll
                for (int nt = 0; nt < 4; nt++) {
                    int n = n0 + nt * 8 + g;
                    uint2 bb = Bs2[(k0 * 512 + n) * 4 + t];
                    bf[nt][0] = bb.x;
                    bf[nt][1] = bb.y;
                }
#pragma unroll
                for (int mt = 0; mt < 2; mt++)
#pragma unroll
                    for (int nt = 0; nt < 4; nt++)
                        mma16816(c[mt][nt][0], c[mt][nt][1], c[mt][nt][2], c[mt][nt][3],
                                 a[k0][mt][0], a[k0][mt][1], a[k0][mt][2], a[k0][mt][3],
                                 bf[nt][0], bf[nt][1]);
            }

            // epilogue: c0,c1 -> row g col 2t,2t+1 ; c2,c3 -> row g+8
#pragma unroll
            for (int mt = 0; mt < 2; mt++) {
                int r0 = mtile * 128 + rbase + mt * 16 + g;
#pragma unroll
                for (int nt = 0; nt < 4; nt++) {
                    int np = (n0 + nt * 8) / 2 + t;
                    zxu[(size_t)r0 * 256 + np]       = b2u(__floats2bfloat162_rn(c[mt][nt][0], c[mt][nt][1]));
                    zxu[(size_t)(r0 + 8) * 256 + np] = b2u(__floats2bfloat162_rn(c[mt][nt][2], c[mt][nt][3]));
                }
            }
        }
    }
}

// ---------------- phase 2: BiLSTM recurrence, h-part only (R13 version, known-good) -------
// grid = 128: dir = blk>>6, group = blk&63 -> batch rows {2g, 2g+1}
__global__ void __launch_bounds__(512, 1)
lstm_kernel(const float* __restrict__ bias_f, const float* __restrict__ bias_b) {
    __shared__ unsigned inb[2 * 64];      // h bf16 pairs, [chain][64]
    __shared__ float zb[2 * 512];

    const int dir = blockIdx.x >> 6;
    const int b0  = (blockIdx.x & 63) * 2;
    const int g   = threadIdx.x;

    const uint4* wp = g_wp2 + dir * (16 * 512);
    __nv_bfloat162 w2[64];
#pragma unroll
    for (int q4 = 0; q4 < 16; q4++) {
        uint4 t = wp[q4 * 512 + g];
        w2[4 * q4 + 0] = u2b(t.x);
        w2[4 * q4 + 1] = u2b(t.y);
        w2[4 * q4 + 2] = u2b(t.z);
        w2[4 * q4 + 3] = u2b(t.w);
    }
    const float bz = (dir ? bias_b : bias_f)[g];
    if (g < 128) inb[g] = 0u;

    const __nv_bfloat16* zxb = g_zx + (size_t)dir * 65536 * 512;
    __nv_bfloat16 zx0c, zx1c, zx0n, zx1n;
    {
        int u0 = dir ? 511 : 0, u1 = dir ? 510 : 1;
        zx0c = zxb[((size_t)(u0 * 128 + b0)) * 512 + g];
        zx1c = zxb[((size_t)(u0 * 128 + b0 + 1)) * 512 + g];
        zx0n = zxb[((size_t)(u1 * 128 + b0)) * 512 + g];
        zx1n = zxb[((size_t)(u1 * 128 + b0 + 1)) * 512 + g];
    }
    float c = 0.0f;
    __syncthreads();

    for (int s = 0; s < Tt; s++) {
        // prefetch zx(s+2); raw bf16 regs, consumed 2 steps later
        __nv_bfloat16 p0 = __float2bfloat16(0.f), p1 = p0;
        if (s + 2 < Tt) {
            int u2 = dir ? (509 - s) : (s + 2);
            p0 = zxb[((size_t)(u2 * 128 + b0)) * 512 + g];
            p1 = zxb[((size_t)(u2 * 128 + b0 + 1)) * 512 + g];
        }

        // h-part GEMM: thread g -> z[r][g], 128 dims, bf16 HFMA2
        __nv_bfloat162 a00 = u2b(0u), a01 = u2b(0u), a10 = u2b(0u), a11 = u2b(0u);
        const uint4* h0 = (const uint4*)inb;
        const uint4* h1 = (const uint4*)(inb + 64);
#pragma unroll
        for (int k = 0; k < 16; k++) {
            uint4 av = h0[k], bv = h1[k];
            a00 = __hfma2(w2[4 * k + 0], u2b(av.x), a00);
            a01 = __hfma2(w2[4 * k + 1], u2b(av.y), a01);
            a00 = __hfma2(w2[4 * k + 2], u2b(av.z), a00);
            a01 = __hfma2(w2[4 * k + 3], u2b(av.w), a01);
            a10 = __hfma2(w2[4 * k + 0], u2b(bv.x), a10);
            a11 = __hfma2(w2[4 * k + 1], u2b(bv.y), a11);
            a10 = __hfma2(w2[4 * k + 2], u2b(bv.z), a10);
            a11 = __hfma2(w2[4 * k + 3], u2b(bv.w), a11);
        }
        {
            float2 f0 = __bfloat1622float2(a00), f1 = __bfloat1622float2(a01);
            zb[g] = (f0.x + f0.y) + (f1.x + f1.y) + bz + __bfloat162float(zx0c);
            f0 = __bfloat1622float2(a10); f1 = __bfloat1622float2(a11);
            zb[512 + g] = (f0.x + f0.y) + (f1.x + f1.y) + bz + __bfloat162float(zx1c);
        }
        __syncthreads();

        if (g < 256) {
            int r = g >> 7, j = g & 127;
            const float* zr = zb + r * 512;
            float zi = zr[j], zf = zr[128 + j], zg_ = zr[256 + j], zo = zr[384 + j];
            c = sig_f(zf) * c + sig_f(zi) * tanh_f(zg_);
            float h = sig_f(zo) * tanh_f(c);
            __nv_bfloat16 hb = __float2bfloat16(h);
            ((__nv_bfloat16*)(inb + r * 64))[j] = hb;
            int u = dir ? (Tt - 1 - s) : s;
            g_h[((size_t)dir * Tt + u) * (Bt * 128) + (b0 + r) * 128 + j] = hb;
        }
        zx0c = zx0n; zx1c = zx1n; zx0n = p0; zx1n = p1;
        __syncthreads();
    }
}

// ---------------- phase 3: feats[b][t][k] = [h_f|h_b] . W_out[k] + b_out[k] ----------------
#define FEATS_SMEM (32 * 132 * 4 + 64 * 128 * 4)   // 49664
__global__ void __launch_bounds__(256)
feats_kernel(const float* __restrict__ W_out, const float* __restrict__ b_out) {
    extern __shared__ __align__(16) char sm[];
    unsigned* Ws = (unsigned*)sm;                  // [32][132] bf16 pairs (padded)
    unsigned* Hs = (unsigned*)(sm + 32 * 132 * 4); // [64][128] bf16 pairs
    int b  = blockIdx.x >> 3;
    int t0 = (blockIdx.x & 7) * 64;
    int tid = threadIdx.x;

    for (int i = tid; i < 32 * 128; i += 256) {
        int k = i >> 7, d2 = i & 127;
        Ws[k * 132 + d2] = b2u(__floats2bfloat162_rn(W_out[k * 256 + 2 * d2],
                                                     W_out[k * 256 + 2 * d2 + 1]));
    }
    const unsigned* ghu = (const unsigned*)g_h;
    for (int i = tid; i < 64 * 128; i += 256) {
        int t = i >> 7, d2 = i & 127;
        int dirb = d2 >> 6, j2 = d2 & 63;
        Hs[t * 128 + d2] = ghu[(((size_t)dirb * Tt + (t0 + t)) * Bt + b) * 64 + j2];
    }
    __syncthreads();

    int k = tid & 31, tg = tid >> 5;
    const uint4* wk = (const uint4*)(Ws + k * 132);
    __nv_bfloat162 acc[8];
#pragma unroll
    for (int tt = 0; tt < 8; tt++) acc[tt] = u2b(0u);
#pragma unroll 4
    for (int q4 = 0; q4 < 32; q4++) {
        uint4 wv = wk[q4];
#pragma unroll
        for (int tt = 0; tt < 8; tt++) {
            uint4 hv = ((const uint4*)(Hs + (tg * 8 + tt) * 128))[q4];
            acc[tt] = __hfma2(u2b(wv.x), u2b(hv.x), acc[tt]);
            acc[tt] = __hfma2(u2b(wv.y), u2b(hv.y), acc[tt]);
            acc[tt] = __hfma2(u2b(wv.z), u2b(hv.z), acc[tt]);
            acc[tt] = __hfma2(u2b(wv.w), u2b(hv.w), acc[tt]);
        }
    }
    float bo = b_out[k];
#pragma unroll
    for (int tt = 0; tt < 8; tt++) {
        float2 f = __bfloat1622float2(acc[tt]);
        g_feats[((size_t)b * Tt + (t0 + tg * 8 + tt)) * KK + k] = f.x + f.y + bo;
    }
}

// ---------------- phase 4: CRF forward logZ (linear ratio-space) + gold score fused -------
__global__ void __launch_bounds__(32)
crf_kernel(const float* __restrict__ trans, const int* __restrict__ tags) {
    const unsigned full = 0xffffffffu;
    __shared__ float qs[2][32];
    int b = blockIdx.x;
    int j = threadIdx.x;
    float et[32];
#pragma unroll
    for (int i = 0; i < 32; i++) et[i] = __expf(trans[j * 32 + i]);   // et[*][0] == 0
    float sumEt = 0.0f;
#pragma unroll
    for (int i = 1; i < 32; i++) sumEt += et[i];
    const float* fbase = g_feats + (size_t)b * Tt * KK;

    float fv0 = fbase[j] + NEGV + __logf(1.0f + sumEt);
    float A = __shfl_sync(full, fv0, 1);
    float qn = __expf(fv0 - A);
    qs[0][j] = qn;
    int buf = 0;
    float rb[4];
#pragma unroll
    for (int d = 0; d < 4; d++) rb[d] = fbase[(1 + d) * KK + j];
    __syncwarp();

    for (int t = 1; t < Tt; t += 4) {
        float ees[4];
#pragma unroll
        for (int d = 0; d < 4; d++) ees[d] = __expf(rb[d]);
#pragma unroll
        for (int d = 0; d < 4; d++) {
            int tn = t + 4 + d; tn = (tn < Tt) ? tn : (Tt - 1);
            rb[d] = fbase[tn * KK + j];
        }
#pragma unroll
        for (int d = 0; d < 4; d++) {
            if (t + d >= Tt) break;
            const float4* qv = (const float4*)qs[buf];
            float s0 = 0.f, s1 = 0.f, s2 = 0.f, s3 = 0.f;
#pragma unroll
            for (int i8 = 0; i8 < 8; i8++) {
                float4 v = qv[i8];
                s0 += et[4 * i8 + 0] * v.x;
                s1 += et[4 * i8 + 1] * v.y;
                s2 += et[4 * i8 + 2] * v.z;
                s3 += et[4 * i8 + 3] * v.w;
            }
            qn = ees[d] * ((s0 + s1) + (s2 + s3));
            if (d & 1) {
                float z = __shfl_sync(full, qn, 1);
                A += __logf(z);
                qn *= rcp_f(z);
            }
            buf ^= 1;
            qs[buf][j] = qn;
            __syncwarp();
        }
    }
    float ss = qn;
#pragma unroll
    for (int o = 16; o; o >>= 1) ss += __shfl_xor_sync(full, ss, o);
    if (j == 0) g_logZ[b] = A + __logf(ss) + NEGV;

    // ---- fused gold path score ----
    const int* tg = tags + b * Tt;
    float acc = 0.0f;
    for (int t = j; t < Tt; t += 32) {
        int cur = tg[t];
        int pv = t ? tg[t - 1] : 0;
        acc += trans[cur * 32 + pv] + fbase[t * KK + cur];
    }
#pragma unroll
    for (int o = 16; o; o >>= 1) acc += __shfl_xor_sync(full, acc, o);
    if (j == 0) g_gold[b] = acc + trans[tg[Tt - 1]];
}

// ---------------- phase 5: deterministic final reduce ----------------
__global__ void final_kernel(float* out) {
    __shared__ float sbuf[128];
    int tid = threadIdx.x;
    sbuf[tid] = g_logZ[tid] - g_gold[tid];
    __syncthreads();
    for (int s2 = 64; s2; s2 >>= 1) {
        if (tid < s2) sbuf[tid] += sbuf[tid + s2];
        __syncthreads();
    }
    if (tid == 0) out[0] = sbuf[0];
}

// ---------------- launch ----------------
extern "C" void kernel_launch(void* const* d_in, const int* in_sizes, int n_in,
                              void* d_out, int out_size) {
    const int*   sentences = (const int*)d_in[0];
    const int*   tags      = (const int*)d_in[1];
    const float* emb       = (const float*)d_in[2];
    const float* Wih_f     = (const float*)d_in[3];
    const float* Whh_f     = (const float*)d_in[4];
    const float* b_f       = (const float*)d_in[5];
    const float* Wih_b     = (const float*)d_in[6];
    const float* Whh_b     = (const float*)d_in[7];
    const float* b_b       = (const float*)d_in[8];
    const float* W_out     = (const float*)d_in[9];
    const float* b_out     = (const float*)d_in[10];
    const float* trans     = (const float*)d_in[11];

    cudaFuncSetAttribute(zx_kernel,    cudaFuncAttributeMaxDynamicSharedMemorySize, ZX_SMEM);
    cudaFuncSetAttribute(feats_kernel, cudaFuncAttributeMaxDynamicSharedMemorySize, FEATS_SMEM);

    prep_w_kernel<<<96, 512>>>(Wih_f, Whh_f, Wih_b, Whh_b);
    zx_kernel<<<dim3(512, 2), 256, ZX_SMEM>>>(sentences, emb);
    lstm_kernel<<<128, 512>>>(b_f, b_b);
    feats_kernel<<<1024, 256, FEATS_SMEM>>>(W_out, b_out);
    crf_kernel<<<128, 32>>>(trans, tags);
    final_kernel<<<1, 128>>>((float*)d_out);
}

// round 17
// speedup vs baseline: 1.0538x; 1.0036x over previous
#include <cuda_runtime.h>
#include <cuda_bf16.h>
#include <stdint.h>

#define Tt 512
#define Bt 128
#define KK 32
#define NEGV (-10000.0f)

// ---------------- scratch (static device globals; no runtime alloc) ----------------
__device__ uint4          g_wp2[2 * 16 * 512];                  // packed bf16x8 Whh [dir][q4][g]
__device__ unsigned       g_wihb[2 * 512 * 32];                 // bf16 Wih [dir][g][64] as u32 pairs
__device__ __nv_bfloat16  g_zx[2ll * 65536 * 512];              // x-projection [dir][m][g]  128 MB
__device__ __nv_bfloat16  g_h[2ll * Tt * Bt * 128];             // [dir][t][b][j]  32 MB
__device__ float          g_feats[(size_t)Bt * Tt * KK];        // [b][t][k]  8 MB
__device__ float          g_logZ[Bt];
__device__ float          g_gold[Bt];

// ---------------- helpers ----------------
__device__ __forceinline__ __nv_bfloat162 u2b(unsigned u) {
    __nv_bfloat162 r; *reinterpret_cast<unsigned*>(&r) = u; return r;
}
__device__ __forceinline__ unsigned b2u(__nv_bfloat162 b) {
    return *reinterpret_cast<unsigned*>(&b);
}
__device__ __forceinline__ float tanh_f(float x) {
    float y; asm("tanh.approx.f32 %0, %1;" : "=f"(y) : "f"(x)); return y;
}
__device__ __forceinline__ float sig_f(float x) { return 0.5f * tanh_f(0.5f * x) + 0.5f; }
__device__ __forceinline__ float rcp_f(float x) {
    float y; asm("rcp.approx.f32 %0, %1;" : "=f"(y) : "f"(x)); return y;
}
__device__ __forceinline__ void mma16816(float& c0, float& c1, float& c2, float& c3,
                                         unsigned a0, unsigned a1, unsigned a2, unsigned a3,
                                         unsigned b0, unsigned b1) {
    asm volatile("mma.sync.aligned.m16n8k16.row.col.f32.bf16.bf16.f32 "
                 "{%0,%1,%2,%3}, {%4,%5,%6,%7}, {%8,%9}, {%0,%1,%2,%3};"
                 : "+f"(c0), "+f"(c1), "+f"(c2), "+f"(c3)
                 : "r"(a0), "r"(a1), "r"(a2), "r"(a3), "r"(b0), "r"(b1));
}

// ---------------- phase 0: pack Whh (bf16x8 per thread-gate) + Wih (bf16 rows) ------------
__global__ void prep_w_kernel(const float* __restrict__ Wih_f, const float* __restrict__ Whh_f,
                              const float* __restrict__ Wih_b, const float* __restrict__ Whh_b) {
    int idx = blockIdx.x * blockDim.x + threadIdx.x;   // 16384 + 32768 = 49152
    if (idx < 16384) {
        int dir = idx >> 13;
        int rem = idx & 8191;
        int q4 = rem >> 9, g = rem & 511;
        const float* Whh = dir ? Whh_b : Whh_f;
        unsigned p[4];
#pragma unroll
        for (int c = 0; c < 4; c++) {
            int d0 = q4 * 8 + 2 * c;
            p[c] = b2u(__floats2bfloat162_rn(Whh[g * 128 + d0], Whh[g * 128 + d0 + 1]));
        }
        g_wp2[idx] = make_uint4(p[0], p[1], p[2], p[3]);
    } else if (idx < 49152) {
        int i2 = idx - 16384;               // 0..32767
        int dir = i2 >> 14;
        int rem = i2 & 16383;
        int g = rem >> 5, p = rem & 31;
        const float* Wih = dir ? Wih_b : Wih_f;
        g_wihb[i2] = b2u(__floats2bfloat162_rn(Wih[g * 64 + 2 * p], Wih[g * 64 + 2 * p + 1]));
    }
}

// ---------------- phase 1: zx = x @ Wih^T — smem-staged mma.sync, 64-bit fragment loads ---
// (R16 version, known-good)
#define ZX_SMEM (4 * 128 * 4 * 8 + 4 * 512 * 4 * 8)   // 16384 + 65536 = 81920
__global__ void __launch_bounds__(256, 2) zx_kernel(const int* __restrict__ sentences,
                                                    const float* __restrict__ emb) {
    extern __shared__ __align__(16) unsigned sm_u[];
    unsigned* As = sm_u;                    // uint2[4][128][4] viewed as u32
    unsigned* Bs = sm_u + 4 * 128 * 4 * 2;  // uint2[4][512][4] viewed as u32

    const int tid   = threadIdx.x;
    const int mtile = blockIdx.x;           // timestep t
    const int dir   = blockIdx.y;

    {
        int row = tid >> 1, hf = tid & 1;   // 2 threads per row
        int tok = sentences[row * Tt + mtile];
        const float4* e4 = (const float4*)(emb + (size_t)tok * 64 + hf * 32);
#pragma unroll
        for (int q = 0; q < 8; q++) {
            float4 v = e4[q];
            int pp0 = hf * 16 + 2 * q;
            int pp1 = pp0 + 1;
            int s0 = pp0 & 7, s1 = pp1 & 7;
            As[(((pp0 >> 3) * 128 + row) * 4 + (s0 & 3)) * 2 + (s0 >> 2)] =
                b2u(__floats2bfloat162_rn(v.x, v.y));
            As[(((pp1 >> 3) * 128 + row) * 4 + (s1 & 3)) * 2 + (s1 >> 2)] =
                b2u(__floats2bfloat162_rn(v.z, v.w));
        }
    }
    {
        const uint4* wu4 = (const uint4*)(g_wihb + dir * 16384);
        for (int i = tid; i < 512 * 8; i += 256) {
            int n = i >> 3, ch = i & 7;
            uint4 v = wu4[n * 8 + ch];
            unsigned vv[4] = {v.x, v.y, v.z, v.w};
#pragma unroll
            for (int c = 0; c < 4; c++) {
                int p = ch * 4 + c;
                int s = p & 7;
                Bs[(((p >> 3) * 512 + n) * 4 + (s & 3)) * 2 + (s >> 2)] = vv[c];
            }
        }
    }
    __syncthreads();

    const int w = tid >> 5, lane = tid & 31;
    const int g = lane >> 2, t = lane & 3;
    const int mwarp = w >> 2, nwarp = w & 3;
    unsigned* zxu = (unsigned*)g_zx + (size_t)dir * 65536 * 256;
    const uint2* As2 = (const uint2*)As;
    const uint2* Bs2 = (const uint2*)Bs;

#pragma unroll 1
    for (int miter = 0; miter < 2; miter++) {
        const int rbase = miter * 64 + mwarp * 32;

        unsigned a[4][2][4];
#pragma unroll
        for (int k0 = 0; k0 < 4; k0++)
#pragma unroll
            for (int mt = 0; mt < 2; mt++) {
                int r0 = rbase + mt * 16;
                uint2 lo = As2[(k0 * 128 + r0 + g) * 4 + t];
                uint2 hi = As2[(k0 * 128 + r0 + 8 + g) * 4 + t];
                a[k0][mt][0] = lo.x;
                a[k0][mt][1] = hi.x;
                a[k0][mt][2] = lo.y;
                a[k0][mt][3] = hi.y;
            }

#pragma unroll 1
        for (int niter = 0; niter < 4; niter++) {
            const int n0 = niter * 128 + nwarp * 32;
            float c[2][4][4];
#pragma unroll
            for (int mt = 0; mt < 2; mt++)
#pragma unroll
                for (int nt = 0; nt < 4; nt++)
#pragma unroll
                    for (int i = 0; i < 4; i++) c[mt][nt][i] = 0.0f;

#pragma unroll
            for (int k0 = 0; k0 < 4; k0++) {
                unsigned bf[4][2];
#pragma unroll
                for (int nt = 0; nt < 4; nt++) {
                    int n = n0 + nt * 8 + g;
                    uint2 bb = Bs2[(k0 * 512 + n) * 4 + t];
                    bf[nt][0] = bb.x;
                    bf[nt][1] = bb.y;
                }
#pragma unroll
                for (int mt = 0; mt < 2; mt++)
#pragma unroll
                    for (int nt = 0; nt < 4; nt++)
                        mma16816(c[mt][nt][0], c[mt][nt][1], c[mt][nt][2], c[mt][nt][3],
                                 a[k0][mt][0], a[k0][mt][1], a[k0][mt][2], a[k0][mt][3],
                                 bf[nt][0], bf[nt][1]);
            }

#pragma unroll
            for (int mt = 0; mt < 2; mt++) {
                int r0 = mtile * 128 + rbase + mt * 16 + g;
#pragma unroll
                for (int nt = 0; nt < 4; nt++) {
                    int np = (n0 + nt * 8) / 2 + t;
                    zxu[(size_t)r0 * 256 + np]       = b2u(__floats2bfloat162_rn(c[mt][nt][0], c[mt][nt][1]));
                    zxu[(size_t)(r0 + 8) * 256 + np] = b2u(__floats2bfloat162_rn(c[mt][nt][2], c[mt][nt][3]));
                }
            }
        }
    }
}

// ---------------- phase 2: BiLSTM — warp-specialized, chains software-pipelined -----------
// grid = 128: dir = blk>>6, group = blk&63 -> batch rows {2g, 2g+1}
// 640 threads: tid<512 = GEMM (gate column g, Whh in regs); tid 512..639 = gate threads.
// step: GEMM0 -> zb0 ; sync ; [gates0 || GEMM1 -> zb1] ; sync ; [gates1 || next GEMM0]
__global__ void __launch_bounds__(640, 1)
lstm_kernel(const float* __restrict__ bias_f, const float* __restrict__ bias_b) {
    __shared__ unsigned inb0[64], inb1[64];   // h bf16 pairs per chain
    __shared__ float zb0[512], zb1[512];

    const int dir = blockIdx.x >> 6;
    const int b0  = (blockIdx.x & 63) * 2;
    const int tid = threadIdx.x;

    if (tid < 512) {
        // ---------------- GEMM threads ----------------
        const int g = tid;
        const uint4* wp = g_wp2 + dir * (16 * 512);
        __nv_bfloat162 w2[64];
#pragma unroll
        for (int q4 = 0; q4 < 16; q4++) {
            uint4 t = wp[q4 * 512 + g];
            w2[4 * q4 + 0] = u2b(t.x);
            w2[4 * q4 + 1] = u2b(t.y);
            w2[4 * q4 + 2] = u2b(t.z);
            w2[4 * q4 + 3] = u2b(t.w);
        }
        const float bz = (dir ? bias_b : bias_f)[g];
        if (g < 64) inb0[g] = 0u;
        else if (g < 128) inb1[g - 64] = 0u;

        const __nv_bfloat16* zxb = g_zx + (size_t)dir * 65536 * 512;
        __nv_bfloat16 zx0c, zx1c, zx0n, zx1n;
        {
            int u0 = dir ? 511 : 0, u1 = dir ? 510 : 1;
            zx0c = zxb[((size_t)(u0 * 128 + b0)) * 512 + g];
            zx1c = zxb[((size_t)(u0 * 128 + b0 + 1)) * 512 + g];
            zx0n = zxb[((size_t)(u1 * 128 + b0)) * 512 + g];
            zx1n = zxb[((size_t)(u1 * 128 + b0 + 1)) * 512 + g];
        }
        __syncthreads();

        for (int s = 0; s < Tt; s++) {
            // prefetch zx(s+2)
            __nv_bfloat16 p0 = __float2bfloat16(0.f), p1 = p0;
            if (s + 2 < Tt) {
                int u2 = dir ? (509 - s) : (s + 2);
                p0 = zxb[((size_t)(u2 * 128 + b0)) * 512 + g];
                p1 = zxb[((size_t)(u2 * 128 + b0 + 1)) * 512 + g];
            }

            // --- GEMM chain 0 ---
            {
                __nv_bfloat162 a00 = u2b(0u), a01 = u2b(0u);
                const uint4* h0 = (const uint4*)inb0;
#pragma unroll
                for (int k = 0; k < 16; k++) {
                    uint4 av = h0[k];
                    a00 = __hfma2(w2[4 * k + 0], u2b(av.x), a00);
                    a01 = __hfma2(w2[4 * k + 1], u2b(av.y), a01);
                    a00 = __hfma2(w2[4 * k + 2], u2b(av.z), a00);
                    a01 = __hfma2(w2[4 * k + 3], u2b(av.w), a01);
                }
                float2 f0 = __bfloat1622float2(a00), f1 = __bfloat1622float2(a01);
                zb0[g] = (f0.x + f0.y) + (f1.x + f1.y) + bz + __bfloat162float(zx0c);
            }
            __syncthreads();   // sync1: zb0 ready -> gates0 ; we proceed to GEMM1

            // --- GEMM chain 1 ---
            {
                __nv_bfloat162 a10 = u2b(0u), a11 = u2b(0u);
                const uint4* h1 = (const uint4*)inb1;
#pragma unroll
                for (int k = 0; k < 16; k++) {
                    uint4 bv = h1[k];
                    a10 = __hfma2(w2[4 * k + 0], u2b(bv.x), a10);
                    a11 = __hfma2(w2[4 * k + 1], u2b(bv.y), a11);
                    a10 = __hfma2(w2[4 * k + 2], u2b(bv.z), a10);
                    a11 = __hfma2(w2[4 * k + 3], u2b(bv.w), a11);
                }
                float2 f0 = __bfloat1622float2(a10), f1 = __bfloat1622float2(a11);
                zb1[g] = (f0.x + f0.y) + (f1.x + f1.y) + bz + __bfloat162float(zx1c);
            }
            zx0c = zx0n; zx1c = zx1n; zx0n = p0; zx1n = p1;
            __syncthreads();   // sync2: zb1 ready -> gates1 ; inb0(s+1) ready -> next GEMM0
        }
    } else {
        // ---------------- gate threads (128) ----------------
        const int j = tid - 512;     // 0..127
        float c0 = 0.0f, c1 = 0.0f;
        __nv_bfloat16* gh = g_h + (size_t)dir * Tt * (Bt * 128);
        __syncthreads();

        for (int s = 0; s < Tt; s++) {
            const int u = dir ? (Tt - 1 - s) : s;
            __syncthreads();   // sync1: zb0 ready
            {
                float zi = zb0[j], zf = zb0[128 + j], zg_ = zb0[256 + j], zo = zb0[384 + j];
                c0 = sig_f(zf) * c0 + sig_f(zi) * tanh_f(zg_);
                float h = sig_f(zo) * tanh_f(c0);
                __nv_bfloat16 hb = __float2bfloat16(h);
                ((__nv_bfloat16*)inb0)[j] = hb;
                gh[(size_t)u * (Bt * 128) + b0 * 128 + j] = hb;
            }
            __syncthreads();   // sync2: zb1 ready
            {
                float zi = zb1[j], zf = zb1[128 + j], zg_ = zb1[256 + j], zo = zb1[384 + j];
                c1 = sig_f(zf) * c1 + sig_f(zi) * tanh_f(zg_);
                float h = sig_f(zo) * tanh_f(c1);
                __nv_bfloat16 hb = __float2bfloat16(h);
                ((__nv_bfloat16*)inb1)[j] = hb;
                gh[(size_t)u * (Bt * 128) + (b0 + 1) * 128 + j] = hb;
            }
        }
    }
}

// ---------------- phase 3: feats[b][t][k] = [h_f|h_b] . W_out[k] + b_out[k] ----------------
#define FEATS_SMEM (32 * 132 * 4 + 64 * 128 * 4)   // 49664
__global__ void __launch_bounds__(256)
feats_kernel(const float* __restrict__ W_out, const float* __restrict__ b_out) {
    extern __shared__ __align__(16) char sm[];
    unsigned* Ws = (unsigned*)sm;                  // [32][132] bf16 pairs (padded)
    unsigned* Hs = (unsigned*)(sm + 32 * 132 * 4); // [64][128] bf16 pairs
    int b  = blockIdx.x >> 3;
    int t0 = (blockIdx.x & 7) * 64;
    int tid = threadIdx.x;

    for (int i = tid; i < 32 * 128; i += 256) {
        int k = i >> 7, d2 = i & 127;
        Ws[k * 132 + d2] = b2u(__floats2bfloat162_rn(W_out[k * 256 + 2 * d2],
                                                     W_out[k * 256 + 2 * d2 + 1]));
    }
    const unsigned* ghu = (const unsigned*)g_h;
    for (int i = tid; i < 64 * 128; i += 256) {
        int t = i >> 7, d2 = i & 127;
        int dirb = d2 >> 6, j2 = d2 & 63;
        Hs[t * 128 + d2] = ghu[(((size_t)dirb * Tt + (t0 + t)) * Bt + b) * 64 + j2];
    }
    __syncthreads();

    int k = tid & 31, tg = tid >> 5;
    const uint4* wk = (const uint4*)(Ws + k * 132);
    __nv_bfloat162 acc[8];
#pragma unroll
    for (int tt = 0; tt < 8; tt++) acc[tt] = u2b(0u);
#pragma unroll 4
    for (int q4 = 0; q4 < 32; q4++) {
        uint4 wv = wk[q4];
#pragma unroll
        for (int tt = 0; tt < 8; tt++) {
            uint4 hv = ((const uint4*)(Hs + (tg * 8 + tt) * 128))[q4];
            acc[tt] = __hfma2(u2b(wv.x), u2b(hv.x), acc[tt]);
            acc[tt] = __hfma2(u2b(wv.y), u2b(hv.y), acc[tt]);
            acc[tt] = __hfma2(u2b(wv.z), u2b(hv.z), acc[tt]);
            acc[tt] = __hfma2(u2b(wv.w), u2b(hv.w), acc[tt]);
        }
    }
    float bo = b_out[k];
#pragma unroll
    for (int tt = 0; tt < 8; tt++) {
        float2 f = __bfloat1622float2(acc[tt]);
        g_feats[((size_t)b * Tt + (t0 + tg * 8 + tt)) * KK + k] = f.x + f.y + bo;
    }
}

// ---------------- phase 4: CRF forward logZ (linear ratio-space) + gold score fused -------
__global__ void __launch_bounds__(32)
crf_kernel(const float* __restrict__ trans, const int* __restrict__ tags) {
    const unsigned full = 0xffffffffu;
    __shared__ float qs[2][32];
    int b = blockIdx.x;
    int j = threadIdx.x;
    float et[32];
#pragma unroll
    for (int i = 0; i < 32; i++) et[i] = __expf(trans[j * 32 + i]);   // et[*][0] == 0
    float sumEt = 0.0f;
#pragma unroll
    for (int i = 1; i < 32; i++) sumEt += et[i];
    const float* fbase = g_feats + (size_t)b * Tt * KK;

    float fv0 = fbase[j] + NEGV + __logf(1.0f + sumEt);
    float A = __shfl_sync(full, fv0, 1);
    float qn = __expf(fv0 - A);
    qs[0][j] = qn;
    int buf = 0;
    float rb[4];
#pragma unroll
    for (int d = 0; d < 4; d++) rb[d] = fbase[(1 + d) * KK + j];
    __syncwarp();

    for (int t = 1; t < Tt; t += 4) {
        float ees[4];
#pragma unroll
        for (int d = 0; d < 4; d++) ees[d] = __expf(rb[d]);
#pragma unroll
        for (int d = 0; d < 4; d++) {
            int tn = t + 4 + d; tn = (tn < Tt) ? tn : (Tt - 1);
            rb[d] = fbase[tn * KK + j];
        }
#pragma unroll
        for (int d = 0; d < 4; d++) {
            if (t + d >= Tt) break;
            const float4* qv = (const float4*)qs[buf];
            float s0 = 0.f, s1 = 0.f, s2 = 0.f, s3 = 0.f;
#pragma unroll
            for (int i8 = 0; i8 < 8; i8++) {
                float4 v = qv[i8];
                s0 += et[4 * i8 + 0] * v.x;
                s1 += et[4 * i8 + 1] * v.y;
                s2 += et[4 * i8 + 2] * v.z;
                s3 += et[4 * i8 + 3] * v.w;
            }
            qn = ees[d] * ((s0 + s1) + (s2 + s3));
            if (d & 1) {
                float z = __shfl_sync(full, qn, 1);
                A += __logf(z);
                qn *= rcp_f(z);
            }
            buf ^= 1;
            qs[buf][j] = qn;
            __syncwarp();
        }
    }
    float ss = qn;
#pragma unroll
    for (int o = 16; o; o >>= 1) ss += __shfl_xor_sync(full, ss, o);
    if (j == 0) g_logZ[b] = A + __logf(ss) + NEGV;

    // ---- fused gold path score ----
    const int* tg = tags + b * Tt;
    float acc = 0.0f;
    for (int t = j; t < Tt; t += 32) {
        int cur = tg[t];
        int pv = t ? tg[t - 1] : 0;
        acc += trans[cur * 32 + pv] + fbase[t * KK + cur];
    }
#pragma unroll
    for (int o = 16; o; o >>= 1) acc += __shfl_xor_sync(full, acc, o);
    if (j == 0) g_gold[b] = acc + trans[tg[Tt - 1]];
}

// ---------------- phase 5: deterministic final reduce ----------------
__global__ void final_kernel(float* out) {
    __shared__ float sbuf[128];
    int tid = threadIdx.x;
    sbuf[tid] = g_logZ[tid] - g_gold[tid];
    __syncthreads();
    for (int s2 = 64; s2; s2 >>= 1) {
        if (tid < s2) sbuf[tid] += sbuf[tid + s2];
        __syncthreads();
    }
    if (tid == 0) out[0] = sbuf[0];
}

// ---------------- launch ----------------
extern "C" void kernel_launch(void* const* d_in, const int* in_sizes, int n_in,
                              void* d_out, int out_size) {
    const int*   sentences = (const int*)d_in[0];
    const int*   tags      = (const int*)d_in[1];
    const float* emb       = (const float*)d_in[2];
    const float* Wih_f     = (const float*)d_in[3];
    const float* Whh_f     = (const float*)d_in[4];
    const float* b_f       = (const float*)d_in[5];
    const float* Wih_b     = (const float*)d_in[6];
    const float* Whh_b     = (const float*)d_in[7];
    const float* b_b       = (const float*)d_in[8];
    const float* W_out     = (const float*)d_in[9];
    const float* b_out     = (const float*)d_in[10];
    const float* trans     = (const float*)d_in[11];

    cudaFuncSetAttribute(zx_kernel,    cudaFuncAttributeMaxDynamicSharedMemorySize, ZX_SMEM);
    cudaFuncSetAttribute(feats_kernel, cudaFuncAttributeMaxDynamicSharedMemorySize, FEATS_SMEM);

    prep_w_kernel<<<96, 512>>>(Wih_f, Whh_f, Wih_b, Whh_b);
    zx_kernel<<<dim3(512, 2), 256, ZX_SMEM>>>(sentences, emb);
    lstm_kernel<<<128, 640>>>(b_f, b_b);
    feats_kernel<<<1024, 256, FEATS_SMEM>>>(W_out, b_out);
    crf_kernel<<<128, 32>>>(trans, tags);
    final_kernel<<<1, 128>>>((float*)d_out);
}